// round 2
// baseline (speedup 1.0000x reference)
#include <cuda_runtime.h>
#include <cstddef>

#define NNODES 100000
#define NEDGES 1600000
#define NFEAT  7
#define HID    128
#define NGRAPH 8
#define NCLASS 5

// Scratch (device globals: allocation-free contract)
__device__ float g_agg[NNODES * HID];   // aggregation buffer (used as [N,7] in layer 1)
__device__ float g_ha[NNODES * HID];    // h1 / h3
__device__ float g_hb[NNODES * HID];    // h2
__device__ float g_pool[NGRAPH * HID];  // graph feature sums
__device__ float g_cnt[NGRAPH];         // graph node counts

// ---------------------------------------------------------------------------
// Layer 1 scatter: thread per edge, 7 features, scalar RED
// ---------------------------------------------------------------------------
__global__ void scatter7(const float* __restrict__ x, const int* __restrict__ ei,
                         const float* __restrict__ ea, const float* __restrict__ We,
                         const float* __restrict__ be) {
    int e = blockIdx.x * blockDim.x + threadIdx.x;
    if (e >= NEDGES) return;
    int s = ei[e];
    int d = ei[NEDGES + e];
    float a = ea[e];
#pragma unroll
    for (int f = 0; f < NFEAT; f++) {
        float m = x[s * NFEAT + f] + fmaf(a, __ldg(&We[f]), __ldg(&be[f]));
        m = fmaxf(m, 0.f);
        atomicAdd(&g_agg[d * NFEAT + f], m);
    }
}

// ---------------------------------------------------------------------------
// Layer 1 dense: h1[n,j] = relu( sum_k (agg+x)[n,k] * W1[k,j] + b1[j] )
// 128 threads per block (one per output col), 256 nodes per block
// ---------------------------------------------------------------------------
__global__ void dense7(const float* __restrict__ x, const float* __restrict__ W,
                       const float* __restrict__ b) {
    __shared__ float sW[NFEAT * HID];
    __shared__ float sb[HID];
    int t = threadIdx.x;  // 0..127
    for (int i = t; i < NFEAT * HID; i += 128) sW[i] = W[i];
    sb[t] = b[t];
    __syncthreads();

    int n0 = blockIdx.x * 256;
    int n1 = n0 + 256; if (n1 > NNODES) n1 = NNODES;
    for (int n = n0; n < n1; n++) {
        float acc = sb[t];
#pragma unroll
        for (int k = 0; k < NFEAT; k++) {
            float v = g_agg[n * NFEAT + k] + __ldg(&x[n * NFEAT + k]);
            acc = fmaf(v, sW[k * HID + t], acc);
        }
        g_ha[(size_t)n * HID + t] = fmaxf(acc, 0.f);
    }
}

// ---------------------------------------------------------------------------
// Dense-layer scatter: warp per edge, 128 features, vector RED (v4.f32)
// ---------------------------------------------------------------------------
__global__ void scatter128(const float* __restrict__ hin, const int* __restrict__ ei,
                           const float* __restrict__ ea, const float* __restrict__ We,
                           const float* __restrict__ be) {
    int warp = (blockIdx.x * blockDim.x + threadIdx.x) >> 5;
    int lane = threadIdx.x & 31;
    if (warp >= NEDGES) return;
    int s = 0, d = 0; float a = 0.f;
    if (lane == 0) { s = ei[warp]; d = ei[NEDGES + warp]; a = ea[warp]; }
    s = __shfl_sync(0xffffffffu, s, 0);
    d = __shfl_sync(0xffffffffu, d, 0);
    a = __shfl_sync(0xffffffffu, a, 0);

    float4 w  = __ldg(&((const float4*)We)[lane]);
    float4 bb = __ldg(&((const float4*)be)[lane]);
    float4 v  = ((const float4*)(hin + (size_t)s * HID))[lane];

    float m0 = fmaxf(v.x + fmaf(a, w.x, bb.x), 0.f);
    float m1 = fmaxf(v.y + fmaf(a, w.y, bb.y), 0.f);
    float m2 = fmaxf(v.z + fmaf(a, w.z, bb.z), 0.f);
    float m3 = fmaxf(v.w + fmaf(a, w.w, bb.w), 0.f);

    float* p = &g_agg[(size_t)d * HID + lane * 4];
    asm volatile("red.global.add.v4.f32 [%0], {%1,%2,%3,%4};"
                 :: "l"(p), "f"(m0), "f"(m1), "f"(m2), "f"(m3) : "memory");
}

// ---------------------------------------------------------------------------
// Dense 128x128: out[n,:] = relu( (A1[n,:]+A2[n,:]) @ W + b )
// Tile: 64 nodes x 128 outs, 256 threads, 8x4 register block, W+A in smem
// ---------------------------------------------------------------------------
__global__ void dense128(const float* __restrict__ A1, const float* __restrict__ A2,
                         const float* __restrict__ W, const float* __restrict__ b,
                         float* __restrict__ out) {
    extern __shared__ float sm[];
    float* sW = sm;              // 128*128 floats = 64KB
    float* sA = sm + HID * HID;  // 64*128 floats  = 32KB
    int t = threadIdx.x;         // 0..255
    int m0 = blockIdx.x * 64;

    {   // load W (16384 floats = 4096 float4)
        float4* dW = (float4*)sW;
        const float4* gW = (const float4*)W;
        for (int i = t; i < HID * HID / 4; i += 256) dW[i] = gW[i];
    }
    {   // load A tile = A1 + A2, 64 rows x 32 float4
        float4* dA = (float4*)sA;
        for (int i = t; i < 64 * 32; i += 256) {
            int r = i >> 5, c = i & 31;
            int n = m0 + r;
            float4 v = make_float4(0.f, 0.f, 0.f, 0.f);
            if (n < NNODES) {
                float4 p = ((const float4*)A1)[(size_t)n * 32 + c];
                float4 q = ((const float4*)A2)[(size_t)n * 32 + c];
                v.x = p.x + q.x; v.y = p.y + q.y; v.z = p.z + q.z; v.w = p.w + q.w;
            }
            dA[i] = v;
        }
    }
    __syncthreads();

    int tn = t & 31;   // output cols tn*4..tn*4+3
    int tm = t >> 5;   // node rows tm*8..tm*8+7
    float acc[8][4];
#pragma unroll
    for (int i = 0; i < 8; i++)
#pragma unroll
        for (int j = 0; j < 4; j++) acc[i][j] = 0.f;

#pragma unroll 8
    for (int k4 = 0; k4 < 32; k4++) {
        float4 a4[8];
#pragma unroll
        for (int i = 0; i < 8; i++)
            a4[i] = ((float4*)(sA + (tm * 8 + i) * HID))[k4];
#pragma unroll
        for (int kk = 0; kk < 4; kk++) {
            float4 w4 = ((float4*)(sW + (k4 * 4 + kk) * HID))[tn];
#pragma unroll
            for (int i = 0; i < 8; i++) {
                float av = (kk == 0) ? a4[i].x : (kk == 1) ? a4[i].y
                         : (kk == 2) ? a4[i].z : a4[i].w;
                acc[i][0] = fmaf(av, w4.x, acc[i][0]);
                acc[i][1] = fmaf(av, w4.y, acc[i][1]);
                acc[i][2] = fmaf(av, w4.z, acc[i][2]);
                acc[i][3] = fmaf(av, w4.w, acc[i][3]);
            }
        }
    }

    float4 bb = __ldg(&((const float4*)b)[tn]);
#pragma unroll
    for (int i = 0; i < 8; i++) {
        int n = m0 + tm * 8 + i;
        if (n < NNODES) {
            float4 o;
            o.x = fmaxf(acc[i][0] + bb.x, 0.f);
            o.y = fmaxf(acc[i][1] + bb.y, 0.f);
            o.z = fmaxf(acc[i][2] + bb.z, 0.f);
            o.w = fmaxf(acc[i][3] + bb.w, 0.f);
            ((float4*)out)[(size_t)n * 32 + tn] = o;
        }
    }
}

// ---------------------------------------------------------------------------
// Pooling
// ---------------------------------------------------------------------------
__global__ void pool_init() {
    int t = blockIdx.x * blockDim.x + threadIdx.x;
    if (t < NGRAPH * HID) g_pool[t] = 0.f;
    if (t < NGRAPH) g_cnt[t] = 0.f;
}

__global__ void pool_kernel(const float* __restrict__ h, const int* __restrict__ batch) {
    int f = threadIdx.x;  // 0..127
    int n0 = blockIdx.x * 256;
    int n1 = n0 + 256; if (n1 > NNODES) n1 = NNODES;
    if (n0 >= NNODES) return;
    float acc = 0.f, c = 0.f;
    int curg = batch[n0];
    for (int n = n0; n < n1; n++) {
        int g = batch[n];
        if (g != curg) {
            atomicAdd(&g_pool[curg * HID + f], acc);
            if (f == 0) atomicAdd(&g_cnt[curg], c);
            acc = 0.f; c = 0.f; curg = g;
        }
        acc += h[(size_t)n * HID + f];
        c += 1.f;
    }
    atomicAdd(&g_pool[curg * HID + f], acc);
    if (f == 0) atomicAdd(&g_cnt[curg], c);
}

__global__ void final_kernel(const float* __restrict__ Wlin, const float* __restrict__ blin,
                             float* __restrict__ out) {
    int t = threadIdx.x;
    if (t >= NGRAPH * NCLASS) return;
    int g = t / NCLASS, c = t % NCLASS;
    float cnt = fmaxf(g_cnt[g], 1.f);
    float acc = blin[c];
#pragma unroll 8
    for (int f = 0; f < HID; f++)
        acc = fmaf(g_pool[g * HID + f] / cnt, Wlin[f * NCLASS + c], acc);
    out[t] = acc;
}

// ---------------------------------------------------------------------------
// Launch
// ---------------------------------------------------------------------------
extern "C" void kernel_launch(void* const* d_in, const int* in_sizes, int n_in,
                              void* d_out, int out_size) {
    const float* x     = (const float*)d_in[0];
    const int*   ei    = (const int*)d_in[1];
    const float* ea    = (const float*)d_in[2];
    const int*   batch = (const int*)d_in[3];
    const float* We1 = (const float*)d_in[4],  *be1 = (const float*)d_in[5];
    const float* W1  = (const float*)d_in[6],  *b1  = (const float*)d_in[7];
    const float* We2 = (const float*)d_in[8],  *be2 = (const float*)d_in[9];
    const float* W2  = (const float*)d_in[10], *b2  = (const float*)d_in[11];
    const float* We3 = (const float*)d_in[12], *be3 = (const float*)d_in[13];
    const float* W3  = (const float*)d_in[14], *b3  = (const float*)d_in[15];
    const float* Wlin = (const float*)d_in[16], *blin = (const float*)d_in[17];
    float* out = (float*)d_out;

    void *aggp, *hap, *hbp;
    cudaGetSymbolAddress(&aggp, g_agg);
    cudaGetSymbolAddress(&hap,  g_ha);
    cudaGetSymbolAddress(&hbp,  g_hb);
    float* agg = (float*)aggp;
    float* ha  = (float*)hap;
    float* hb  = (float*)hbp;

    cudaFuncSetAttribute(dense128, cudaFuncAttributeMaxDynamicSharedMemorySize, 98304);

    const int SC128_BLOCKS = NEDGES / 8;           // 8 warps (edges) per block
    const int D128_BLOCKS  = (NNODES + 63) / 64;

    // Layer 1 (in = 7 feats)
    cudaMemsetAsync(aggp, 0, (size_t)NNODES * NFEAT * sizeof(float), 0);
    scatter7<<<(NEDGES + 255) / 256, 256>>>(x, ei, ea, We1, be1);
    dense7<<<(NNODES + 255) / 256, 128>>>(x, W1, b1);                 // -> g_ha

    // Layer 2
    cudaMemsetAsync(aggp, 0, (size_t)NNODES * HID * sizeof(float), 0);
    scatter128<<<SC128_BLOCKS, 256>>>(ha, ei, ea, We2, be2);
    dense128<<<D128_BLOCKS, 256, 98304>>>(agg, ha, W2, b2, hb);       // -> g_hb

    // Layer 3
    cudaMemsetAsync(aggp, 0, (size_t)NNODES * HID * sizeof(float), 0);
    scatter128<<<SC128_BLOCKS, 256>>>(hb, ei, ea, We3, be3);
    dense128<<<D128_BLOCKS, 256, 98304>>>(agg, hb, W3, b3, ha);       // -> g_ha

    // Mean pool + linear head
    pool_init<<<8, 128>>>();
    pool_kernel<<<(NNODES + 255) / 256, 128>>>(ha, batch);
    final_kernel<<<1, 64>>>(Wlin, blin, out);
}

// round 3
// speedup vs baseline: 1.3079x; 1.3079x over previous
#include <cuda_runtime.h>
#include <cstddef>

#define NNODES 100000
#define NEDGES 1600000
#define NFEAT  7
#define HID    128
#define NGRAPH 8
#define NCLASS 5

// ---------------------------------------------------------------------------
// Device-global scratch (allocation-free contract)
// ---------------------------------------------------------------------------
__device__ int   g_rowptr[NNODES + 1];
__device__ int   g_cur[NNODES];          // degree histogram, then fill cursor
__device__ int   g_csrc[NEDGES];         // CSR: src node per slot
__device__ float g_ca[NEDGES];           // CSR: edge attr per slot
__device__ float g_agg7[NNODES * NFEAT];
__device__ float g_agg[NNODES * HID];
__device__ float g_ha[NNODES * HID];
__device__ float g_hb[NNODES * HID];
__device__ float g_pool[NGRAPH * HID];
__device__ float g_cnt[NGRAPH];

// ---------------------------------------------------------------------------
// CSR build: histogram -> scan -> fill
// ---------------------------------------------------------------------------
__global__ void hist_kernel(const int* __restrict__ ei) {
    int e = blockIdx.x * blockDim.x + threadIdx.x;
    if (e < NEDGES) atomicAdd(&g_cur[ei[NEDGES + e]], 1);
}

// Single-block (1024 threads) sequential chunked exclusive scan of g_cur
// -> g_rowptr (and re-writes g_cur with the same exclusive offsets as cursors)
__global__ void scan_kernel() {
    __shared__ int warp_sums[32];
    __shared__ int s_carry;
    int tid = threadIdx.x;
    int lane = tid & 31, wid = tid >> 5;
    if (tid == 0) s_carry = 0;
    __syncthreads();
    for (int base = 0; base < NNODES; base += 1024) {
        int i = base + tid;
        int v = (i < NNODES) ? g_cur[i] : 0;
        int incl = v;
#pragma unroll
        for (int o = 1; o < 32; o <<= 1) {
            int t = __shfl_up_sync(0xffffffffu, incl, o);
            if (lane >= o) incl += t;
        }
        if (lane == 31) warp_sums[wid] = incl;
        __syncthreads();
        if (wid == 0) {
            int ws = warp_sums[lane];
            int wincl = ws;
#pragma unroll
            for (int o = 1; o < 32; o <<= 1) {
                int t = __shfl_up_sync(0xffffffffu, wincl, o);
                if (lane >= o) wincl += t;
            }
            warp_sums[lane] = wincl - ws;  // exclusive warp offset
        }
        __syncthreads();
        int excl = incl - v + warp_sums[wid] + s_carry;
        if (i < NNODES) { g_rowptr[i] = excl; g_cur[i] = excl; }
        __syncthreads();
        if (tid == 1023) s_carry = excl + v;
        __syncthreads();
    }
    if (tid == 0) g_rowptr[NNODES] = NEDGES;
}

__global__ void fill_kernel(const int* __restrict__ ei, const float* __restrict__ ea) {
    int e = blockIdx.x * blockDim.x + threadIdx.x;
    if (e >= NEDGES) return;
    int d = ei[NEDGES + e];
    int pos = atomicAdd(&g_cur[d], 1);
    g_csrc[pos] = ei[e];
    g_ca[pos]   = ea[e];
}

// ---------------------------------------------------------------------------
// Layer 1 gather: thread per node, 7 features; init acc with x[n] (self term)
// ---------------------------------------------------------------------------
__global__ void gather7(const float* __restrict__ x, const float* __restrict__ We,
                        const float* __restrict__ be) {
    int n = blockIdx.x * blockDim.x + threadIdx.x;
    if (n >= NNODES) return;
    float w[NFEAT], bb[NFEAT], acc[NFEAT];
#pragma unroll
    for (int f = 0; f < NFEAT; f++) { w[f] = __ldg(&We[f]); bb[f] = __ldg(&be[f]); }
#pragma unroll
    for (int f = 0; f < NFEAT; f++) acc[f] = x[n * NFEAT + f];
    int beg = g_rowptr[n], end = g_rowptr[n + 1];
    for (int e = beg; e < end; e++) {
        int s = __ldg(&g_csrc[e]);
        float a = __ldg(&g_ca[e]);
#pragma unroll
        for (int f = 0; f < NFEAT; f++)
            acc[f] += fmaxf(__ldg(&x[s * NFEAT + f]) + fmaf(a, w[f], bb[f]), 0.f);
    }
#pragma unroll
    for (int f = 0; f < NFEAT; f++) g_agg7[n * NFEAT + f] = acc[f];
}

// ---------------------------------------------------------------------------
// Layer 1 dense: h1[n,j] = relu( agg7[n,:] @ W1 + b1 )
// ---------------------------------------------------------------------------
__global__ void dense7(const float* __restrict__ W, const float* __restrict__ b) {
    __shared__ float sW[NFEAT * HID];
    __shared__ float sb[HID];
    int t = threadIdx.x;  // 0..127
    for (int i = t; i < NFEAT * HID; i += 128) sW[i] = W[i];
    sb[t] = b[t];
    __syncthreads();

    int n0 = blockIdx.x * 256;
    int n1 = n0 + 256; if (n1 > NNODES) n1 = NNODES;
    for (int n = n0; n < n1; n++) {
        float acc = sb[t];
#pragma unroll
        for (int k = 0; k < NFEAT; k++)
            acc = fmaf(g_agg7[n * NFEAT + k], sW[k * HID + t], acc);
        g_ha[(size_t)n * HID + t] = fmaxf(acc, 0.f);
    }
}

// ---------------------------------------------------------------------------
// 128-feat gather: warp per node; acc initialized with h[n] (self term)
// ---------------------------------------------------------------------------
__global__ void gather128(const float* __restrict__ hin, const float* __restrict__ We,
                          const float* __restrict__ be, float* __restrict__ aggout) {
    int warp = (blockIdx.x * blockDim.x + threadIdx.x) >> 5;
    int lane = threadIdx.x & 31;
    if (warp >= NNODES) return;
    float4 w  = __ldg(&((const float4*)We)[lane]);
    float4 bb = __ldg(&((const float4*)be)[lane]);
    int beg = __ldg(&g_rowptr[warp]);
    int end = __ldg(&g_rowptr[warp + 1]);
    const float4* h4 = (const float4*)hin;
    float4 acc = h4[(size_t)warp * 32 + lane];

    int e = beg;
    for (; e + 1 < end; e += 2) {
        int   s0 = __ldg(&g_csrc[e]),   s1 = __ldg(&g_csrc[e + 1]);
        float a0 = __ldg(&g_ca[e]),     a1 = __ldg(&g_ca[e + 1]);
        float4 v0 = h4[(size_t)s0 * 32 + lane];
        float4 v1 = h4[(size_t)s1 * 32 + lane];
        acc.x += fmaxf(v0.x + fmaf(a0, w.x, bb.x), 0.f) + fmaxf(v1.x + fmaf(a1, w.x, bb.x), 0.f);
        acc.y += fmaxf(v0.y + fmaf(a0, w.y, bb.y), 0.f) + fmaxf(v1.y + fmaf(a1, w.y, bb.y), 0.f);
        acc.z += fmaxf(v0.z + fmaf(a0, w.z, bb.z), 0.f) + fmaxf(v1.z + fmaf(a1, w.z, bb.z), 0.f);
        acc.w += fmaxf(v0.w + fmaf(a0, w.w, bb.w), 0.f) + fmaxf(v1.w + fmaf(a1, w.w, bb.w), 0.f);
    }
    if (e < end) {
        int   s0 = __ldg(&g_csrc[e]);
        float a0 = __ldg(&g_ca[e]);
        float4 v0 = h4[(size_t)s0 * 32 + lane];
        acc.x += fmaxf(v0.x + fmaf(a0, w.x, bb.x), 0.f);
        acc.y += fmaxf(v0.y + fmaf(a0, w.y, bb.y), 0.f);
        acc.z += fmaxf(v0.z + fmaf(a0, w.z, bb.z), 0.f);
        acc.w += fmaxf(v0.w + fmaf(a0, w.w, bb.w), 0.f);
    }
    ((float4*)aggout)[(size_t)warp * 32 + lane] = acc;
}

// ---------------------------------------------------------------------------
// Dense 128x128: out[n,:] = relu( A[n,:] @ W + b )
// Tile: 64 nodes x 128 outs, 256 threads, 8x4 register block, W+A in smem
// ---------------------------------------------------------------------------
__global__ void dense128(const float* __restrict__ A, const float* __restrict__ W,
                         const float* __restrict__ b, float* __restrict__ out) {
    extern __shared__ float sm[];
    float* sW = sm;              // 128*128 floats = 64KB
    float* sA = sm + HID * HID;  // 64*128 floats  = 32KB
    int t = threadIdx.x;         // 0..255
    int m0 = blockIdx.x * 64;

    {
        float4* dW = (float4*)sW;
        const float4* gW = (const float4*)W;
        for (int i = t; i < HID * HID / 4; i += 256) dW[i] = gW[i];
    }
    {
        float4* dA = (float4*)sA;
        for (int i = t; i < 64 * 32; i += 256) {
            int r = i >> 5, c = i & 31;
            int n = m0 + r;
            float4 v = make_float4(0.f, 0.f, 0.f, 0.f);
            if (n < NNODES) v = ((const float4*)A)[(size_t)n * 32 + c];
            dA[i] = v;
        }
    }
    __syncthreads();

    int tn = t & 31;
    int tm = t >> 5;
    float acc[8][4];
#pragma unroll
    for (int i = 0; i < 8; i++)
#pragma unroll
        for (int j = 0; j < 4; j++) acc[i][j] = 0.f;

#pragma unroll 8
    for (int k4 = 0; k4 < 32; k4++) {
        float4 a4[8];
#pragma unroll
        for (int i = 0; i < 8; i++)
            a4[i] = ((float4*)(sA + (tm * 8 + i) * HID))[k4];
#pragma unroll
        for (int kk = 0; kk < 4; kk++) {
            float4 w4 = ((float4*)(sW + (k4 * 4 + kk) * HID))[tn];
#pragma unroll
            for (int i = 0; i < 8; i++) {
                float av = (kk == 0) ? a4[i].x : (kk == 1) ? a4[i].y
                         : (kk == 2) ? a4[i].z : a4[i].w;
                acc[i][0] = fmaf(av, w4.x, acc[i][0]);
                acc[i][1] = fmaf(av, w4.y, acc[i][1]);
                acc[i][2] = fmaf(av, w4.z, acc[i][2]);
                acc[i][3] = fmaf(av, w4.w, acc[i][3]);
            }
        }
    }

    float4 bb = __ldg(&((const float4*)b)[tn]);
#pragma unroll
    for (int i = 0; i < 8; i++) {
        int n = m0 + tm * 8 + i;
        if (n < NNODES) {
            float4 o;
            o.x = fmaxf(acc[i][0] + bb.x, 0.f);
            o.y = fmaxf(acc[i][1] + bb.y, 0.f);
            o.z = fmaxf(acc[i][2] + bb.z, 0.f);
            o.w = fmaxf(acc[i][3] + bb.w, 0.f);
            ((float4*)out)[(size_t)n * 32 + tn] = o;
        }
    }
}

// ---------------------------------------------------------------------------
// Pooling + head
// ---------------------------------------------------------------------------
__global__ void pool_init() {
    int t = blockIdx.x * blockDim.x + threadIdx.x;
    if (t < NGRAPH * HID) g_pool[t] = 0.f;
    if (t < NGRAPH) g_cnt[t] = 0.f;
}

__global__ void pool_kernel(const float* __restrict__ h, const int* __restrict__ batch) {
    int f = threadIdx.x;  // 0..127
    int n0 = blockIdx.x * 256;
    int n1 = n0 + 256; if (n1 > NNODES) n1 = NNODES;
    if (n0 >= NNODES) return;
    float acc = 0.f, c = 0.f;
    int curg = batch[n0];
    for (int n = n0; n < n1; n++) {
        int g = batch[n];
        if (g != curg) {
            atomicAdd(&g_pool[curg * HID + f], acc);
            if (f == 0) atomicAdd(&g_cnt[curg], c);
            acc = 0.f; c = 0.f; curg = g;
        }
        acc += h[(size_t)n * HID + f];
        c += 1.f;
    }
    atomicAdd(&g_pool[curg * HID + f], acc);
    if (f == 0) atomicAdd(&g_cnt[curg], c);
}

__global__ void final_kernel(const float* __restrict__ Wlin, const float* __restrict__ blin,
                             float* __restrict__ out) {
    int t = threadIdx.x;
    if (t >= NGRAPH * NCLASS) return;
    int g = t / NCLASS, c = t % NCLASS;
    float cnt = fmaxf(g_cnt[g], 1.f);
    float acc = blin[c];
#pragma unroll 8
    for (int f = 0; f < HID; f++)
        acc = fmaf(g_pool[g * HID + f] / cnt, Wlin[f * NCLASS + c], acc);
    out[t] = acc;
}

// ---------------------------------------------------------------------------
// Launch
// ---------------------------------------------------------------------------
extern "C" void kernel_launch(void* const* d_in, const int* in_sizes, int n_in,
                              void* d_out, int out_size) {
    const float* x     = (const float*)d_in[0];
    const int*   ei    = (const int*)d_in[1];
    const float* ea    = (const float*)d_in[2];
    const int*   batch = (const int*)d_in[3];
    const float* We1 = (const float*)d_in[4],  *be1 = (const float*)d_in[5];
    const float* W1  = (const float*)d_in[6],  *b1  = (const float*)d_in[7];
    const float* We2 = (const float*)d_in[8],  *be2 = (const float*)d_in[9];
    const float* W2  = (const float*)d_in[10], *b2  = (const float*)d_in[11];
    const float* We3 = (const float*)d_in[12], *be3 = (const float*)d_in[13];
    const float* W3  = (const float*)d_in[14], *b3  = (const float*)d_in[15];
    const float* Wlin = (const float*)d_in[16], *blin = (const float*)d_in[17];
    float* out = (float*)d_out;

    void *aggp, *hap, *hbp, *curp;
    cudaGetSymbolAddress(&aggp, g_agg);
    cudaGetSymbolAddress(&hap,  g_ha);
    cudaGetSymbolAddress(&hbp,  g_hb);
    cudaGetSymbolAddress(&curp, g_cur);
    float* agg = (float*)aggp;
    float* ha  = (float*)hap;
    float* hb  = (float*)hbp;

    cudaFuncSetAttribute(dense128, cudaFuncAttributeMaxDynamicSharedMemorySize, 98304);

    const int EBLK = (NEDGES + 255) / 256;
    const int G128_BLOCKS = (NNODES * 32 + 255) / 256;   // warp per node
    const int D128_BLOCKS = (NNODES + 63) / 64;

    // CSR build (reused by all 3 layers)
    cudaMemsetAsync(curp, 0, NNODES * sizeof(int), 0);
    hist_kernel<<<EBLK, 256>>>(ei);
    scan_kernel<<<1, 1024>>>();
    fill_kernel<<<EBLK, 256>>>(ei, ea);

    // Layer 1 (in = 7 feats)
    gather7<<<(NNODES + 255) / 256, 256>>>(x, We1, be1);
    dense7<<<(NNODES + 255) / 256, 128>>>(W1, b1);                    // -> g_ha

    // Layer 2
    gather128<<<G128_BLOCKS, 256>>>(ha, We2, be2, agg);
    dense128<<<D128_BLOCKS, 256, 98304>>>(agg, W2, b2, hb);           // -> g_hb

    // Layer 3
    gather128<<<G128_BLOCKS, 256>>>(hb, We3, be3, agg);
    dense128<<<D128_BLOCKS, 256, 98304>>>(agg, W3, b3, ha);           // -> g_ha

    // Mean pool + linear head
    pool_init<<<8, 128>>>();
    pool_kernel<<<(NNODES + 255) / 256, 128>>>(ha, batch);
    final_kernel<<<1, 64>>>(Wlin, blin, out);
}

// round 4
// speedup vs baseline: 1.4313x; 1.0943x over previous
#include <cuda_runtime.h>
#include <cstddef>

#define NNODES 100000
#define NEDGES 1600000
#define NFEAT  7
#define HID    128
#define NGRAPH 8
#define NCLASS 5

// ---------------------------------------------------------------------------
// Device-global scratch (allocation-free contract)
// ---------------------------------------------------------------------------
__device__ int   g_rowptr[NNODES + 1];
__device__ int   g_cur[NNODES];          // degree histogram, then fill cursor
__device__ int   g_csrc[NEDGES];         // CSR: src node per slot
__device__ float g_ca[NEDGES];           // CSR: edge attr per slot
__device__ float g_agg7[NNODES * NFEAT];
__device__ float g_agg[NNODES * HID];
__device__ float g_ha[NNODES * HID];
__device__ float g_hb[NNODES * HID];
__device__ float g_pool[NGRAPH * HID];
__device__ float g_cnt[NGRAPH];

// ---------------------------------------------------------------------------
// CSR build: histogram -> scan -> fill
// ---------------------------------------------------------------------------
__global__ void hist_kernel(const int* __restrict__ ei) {
    int e = blockIdx.x * blockDim.x + threadIdx.x;
    if (e < NEDGES) atomicAdd(&g_cur[ei[NEDGES + e]], 1);
}

__global__ void scan_kernel() {
    __shared__ int warp_sums[32];
    __shared__ int s_carry;
    int tid = threadIdx.x;
    int lane = tid & 31, wid = tid >> 5;
    if (tid == 0) s_carry = 0;
    __syncthreads();
    for (int base = 0; base < NNODES; base += 1024) {
        int i = base + tid;
        int v = (i < NNODES) ? g_cur[i] : 0;
        int incl = v;
#pragma unroll
        for (int o = 1; o < 32; o <<= 1) {
            int t = __shfl_up_sync(0xffffffffu, incl, o);
            if (lane >= o) incl += t;
        }
        if (lane == 31) warp_sums[wid] = incl;
        __syncthreads();
        if (wid == 0) {
            int ws = warp_sums[lane];
            int wincl = ws;
#pragma unroll
            for (int o = 1; o < 32; o <<= 1) {
                int t = __shfl_up_sync(0xffffffffu, wincl, o);
                if (lane >= o) wincl += t;
            }
            warp_sums[lane] = wincl - ws;  // exclusive warp offset
        }
        __syncthreads();
        int excl = incl - v + warp_sums[wid] + s_carry;
        if (i < NNODES) { g_rowptr[i] = excl; g_cur[i] = excl; }
        __syncthreads();
        if (tid == 1023) s_carry = excl + v;
        __syncthreads();
    }
    if (tid == 0) g_rowptr[NNODES] = NEDGES;
}

__global__ void fill_kernel(const int* __restrict__ ei, const float* __restrict__ ea) {
    int e = blockIdx.x * blockDim.x + threadIdx.x;
    if (e >= NEDGES) return;
    int d = ei[NEDGES + e];
    int pos = atomicAdd(&g_cur[d], 1);
    g_csrc[pos] = ei[e];
    g_ca[pos]   = ea[e];
}

// ---------------------------------------------------------------------------
// Layer 1 gather: thread per node, 7 features, 4-edge unroll for MLP
// ---------------------------------------------------------------------------
__global__ void gather7(const float* __restrict__ x, const float* __restrict__ We,
                        const float* __restrict__ be) {
    int n = blockIdx.x * blockDim.x + threadIdx.x;
    if (n >= NNODES) return;
    float w[NFEAT], bb[NFEAT], acc[NFEAT];
#pragma unroll
    for (int f = 0; f < NFEAT; f++) { w[f] = __ldg(&We[f]); bb[f] = __ldg(&be[f]); }
#pragma unroll
    for (int f = 0; f < NFEAT; f++) acc[f] = x[n * NFEAT + f];
    int beg = g_rowptr[n], end = g_rowptr[n + 1];
    int e = beg;
    for (; e + 3 < end; e += 4) {
        int s0 = __ldg(&g_csrc[e]),     s1 = __ldg(&g_csrc[e + 1]);
        int s2 = __ldg(&g_csrc[e + 2]), s3 = __ldg(&g_csrc[e + 3]);
        float a0 = __ldg(&g_ca[e]),     a1 = __ldg(&g_ca[e + 1]);
        float a2 = __ldg(&g_ca[e + 2]), a3 = __ldg(&g_ca[e + 3]);
        float v0[NFEAT], v1[NFEAT], v2[NFEAT], v3[NFEAT];
#pragma unroll
        for (int f = 0; f < NFEAT; f++) v0[f] = __ldg(&x[s0 * NFEAT + f]);
#pragma unroll
        for (int f = 0; f < NFEAT; f++) v1[f] = __ldg(&x[s1 * NFEAT + f]);
#pragma unroll
        for (int f = 0; f < NFEAT; f++) v2[f] = __ldg(&x[s2 * NFEAT + f]);
#pragma unroll
        for (int f = 0; f < NFEAT; f++) v3[f] = __ldg(&x[s3 * NFEAT + f]);
#pragma unroll
        for (int f = 0; f < NFEAT; f++) {
            acc[f] += fmaxf(v0[f] + fmaf(a0, w[f], bb[f]), 0.f)
                    + fmaxf(v1[f] + fmaf(a1, w[f], bb[f]), 0.f)
                    + fmaxf(v2[f] + fmaf(a2, w[f], bb[f]), 0.f)
                    + fmaxf(v3[f] + fmaf(a3, w[f], bb[f]), 0.f);
        }
    }
    for (; e < end; e++) {
        int s = __ldg(&g_csrc[e]);
        float a = __ldg(&g_ca[e]);
#pragma unroll
        for (int f = 0; f < NFEAT; f++)
            acc[f] += fmaxf(__ldg(&x[s * NFEAT + f]) + fmaf(a, w[f], bb[f]), 0.f);
    }
#pragma unroll
    for (int f = 0; f < NFEAT; f++) g_agg7[n * NFEAT + f] = acc[f];
}

// ---------------------------------------------------------------------------
// Layer 1 dense: smem-staged agg tile; h1[n,j] = relu( agg7[n,:] @ W1 + b1 )
// ---------------------------------------------------------------------------
__global__ void dense7(const float* __restrict__ W, const float* __restrict__ b) {
    __shared__ float sW[NFEAT * HID];
    __shared__ float sb[HID];
    __shared__ float sAgg[256 * NFEAT];
    int t = threadIdx.x;  // 0..127
    for (int i = t; i < NFEAT * HID; i += 128) sW[i] = W[i];
    sb[t] = b[t];

    int n0 = blockIdx.x * 256;
    int cnt = NNODES - n0; if (cnt > 256) cnt = 256;
    for (int i = t; i < cnt * NFEAT; i += 128) sAgg[i] = g_agg7[n0 * NFEAT + i];
    __syncthreads();

    for (int r = 0; r < cnt; r++) {
        float acc = sb[t];
#pragma unroll
        for (int k = 0; k < NFEAT; k++)
            acc = fmaf(sAgg[r * NFEAT + k], sW[k * HID + t], acc);
        g_ha[(size_t)(n0 + r) * HID + t] = fmaxf(acc, 0.f);
    }
}

// ---------------------------------------------------------------------------
// 128-feat gather: warp per node, 4-edge unroll (MLP=4)
// ---------------------------------------------------------------------------
__global__ void gather128(const float* __restrict__ hin, const float* __restrict__ We,
                          const float* __restrict__ be, float* __restrict__ aggout) {
    int warp = (blockIdx.x * blockDim.x + threadIdx.x) >> 5;
    int lane = threadIdx.x & 31;
    if (warp >= NNODES) return;
    float4 w  = __ldg(&((const float4*)We)[lane]);
    float4 bb = __ldg(&((const float4*)be)[lane]);
    int beg = __ldg(&g_rowptr[warp]);
    int end = __ldg(&g_rowptr[warp + 1]);
    const float4* h4 = (const float4*)hin;
    float4 acc = h4[(size_t)warp * 32 + lane];

    int e = beg;
    for (; e + 3 < end; e += 4) {
        int   s0 = __ldg(&g_csrc[e]),     s1 = __ldg(&g_csrc[e + 1]);
        int   s2 = __ldg(&g_csrc[e + 2]), s3 = __ldg(&g_csrc[e + 3]);
        float a0 = __ldg(&g_ca[e]),       a1 = __ldg(&g_ca[e + 1]);
        float a2 = __ldg(&g_ca[e + 2]),   a3 = __ldg(&g_ca[e + 3]);
        float4 v0 = h4[(size_t)s0 * 32 + lane];
        float4 v1 = h4[(size_t)s1 * 32 + lane];
        float4 v2 = h4[(size_t)s2 * 32 + lane];
        float4 v3 = h4[(size_t)s3 * 32 + lane];
        acc.x += fmaxf(v0.x + fmaf(a0, w.x, bb.x), 0.f) + fmaxf(v1.x + fmaf(a1, w.x, bb.x), 0.f)
               + fmaxf(v2.x + fmaf(a2, w.x, bb.x), 0.f) + fmaxf(v3.x + fmaf(a3, w.x, bb.x), 0.f);
        acc.y += fmaxf(v0.y + fmaf(a0, w.y, bb.y), 0.f) + fmaxf(v1.y + fmaf(a1, w.y, bb.y), 0.f)
               + fmaxf(v2.y + fmaf(a2, w.y, bb.y), 0.f) + fmaxf(v3.y + fmaf(a3, w.y, bb.y), 0.f);
        acc.z += fmaxf(v0.z + fmaf(a0, w.z, bb.z), 0.f) + fmaxf(v1.z + fmaf(a1, w.z, bb.z), 0.f)
               + fmaxf(v2.z + fmaf(a2, w.z, bb.z), 0.f) + fmaxf(v3.z + fmaf(a3, w.z, bb.z), 0.f);
        acc.w += fmaxf(v0.w + fmaf(a0, w.w, bb.w), 0.f) + fmaxf(v1.w + fmaf(a1, w.w, bb.w), 0.f)
               + fmaxf(v2.w + fmaf(a2, w.w, bb.w), 0.f) + fmaxf(v3.w + fmaf(a3, w.w, bb.w), 0.f);
    }
    for (; e < end; e++) {
        int   s0 = __ldg(&g_csrc[e]);
        float a0 = __ldg(&g_ca[e]);
        float4 v0 = h4[(size_t)s0 * 32 + lane];
        acc.x += fmaxf(v0.x + fmaf(a0, w.x, bb.x), 0.f);
        acc.y += fmaxf(v0.y + fmaf(a0, w.y, bb.y), 0.f);
        acc.z += fmaxf(v0.z + fmaf(a0, w.z, bb.z), 0.f);
        acc.w += fmaxf(v0.w + fmaf(a0, w.w, bb.w), 0.f);
    }
    ((float4*)aggout)[(size_t)warp * 32 + lane] = acc;
}

// ---------------------------------------------------------------------------
// Dense 128x128: out[n,:] = relu( A[n,:] @ W + b )
// Tile: 64 nodes x 128 outs, 256 threads, 8x4 register block, W+A in smem
// ---------------------------------------------------------------------------
__global__ void dense128(const float* __restrict__ A, const float* __restrict__ W,
                         const float* __restrict__ b, float* __restrict__ out) {
    extern __shared__ float sm[];
    float* sW = sm;              // 128*128 floats = 64KB
    float* sA = sm + HID * HID;  // 64*128 floats  = 32KB
    int t = threadIdx.x;         // 0..255
    int m0 = blockIdx.x * 64;

    {
        float4* dW = (float4*)sW;
        const float4* gW = (const float4*)W;
        for (int i = t; i < HID * HID / 4; i += 256) dW[i] = gW[i];
    }
    {
        float4* dA = (float4*)sA;
        for (int i = t; i < 64 * 32; i += 256) {
            int r = i >> 5, c = i & 31;
            int n = m0 + r;
            float4 v = make_float4(0.f, 0.f, 0.f, 0.f);
            if (n < NNODES) v = ((const float4*)A)[(size_t)n * 32 + c];
            dA[i] = v;
        }
    }
    __syncthreads();

    int tn = t & 31;
    int tm = t >> 5;
    float acc[8][4];
#pragma unroll
    for (int i = 0; i < 8; i++)
#pragma unroll
        for (int j = 0; j < 4; j++) acc[i][j] = 0.f;

#pragma unroll 8
    for (int k4 = 0; k4 < 32; k4++) {
        float4 a4[8];
#pragma unroll
        for (int i = 0; i < 8; i++)
            a4[i] = ((float4*)(sA + (tm * 8 + i) * HID))[k4];
#pragma unroll
        for (int kk = 0; kk < 4; kk++) {
            float4 w4 = ((float4*)(sW + (k4 * 4 + kk) * HID))[tn];
#pragma unroll
            for (int i = 0; i < 8; i++) {
                float av = (kk == 0) ? a4[i].x : (kk == 1) ? a4[i].y
                         : (kk == 2) ? a4[i].z : a4[i].w;
                acc[i][0] = fmaf(av, w4.x, acc[i][0]);
                acc[i][1] = fmaf(av, w4.y, acc[i][1]);
                acc[i][2] = fmaf(av, w4.z, acc[i][2]);
                acc[i][3] = fmaf(av, w4.w, acc[i][3]);
            }
        }
    }

    float4 bb = __ldg(&((const float4*)b)[tn]);
#pragma unroll
    for (int i = 0; i < 8; i++) {
        int n = m0 + tm * 8 + i;
        if (n < NNODES) {
            float4 o;
            o.x = fmaxf(acc[i][0] + bb.x, 0.f);
            o.y = fmaxf(acc[i][1] + bb.y, 0.f);
            o.z = fmaxf(acc[i][2] + bb.z, 0.f);
            o.w = fmaxf(acc[i][3] + bb.w, 0.f);
            ((float4*)out)[(size_t)n * 32 + tn] = o;
        }
    }
}

// ---------------------------------------------------------------------------
// Pooling + head
// ---------------------------------------------------------------------------
__global__ void pool_init() {
    int t = blockIdx.x * blockDim.x + threadIdx.x;
    if (t < NGRAPH * HID) g_pool[t] = 0.f;
    if (t < NGRAPH) g_cnt[t] = 0.f;
}

__global__ void pool_kernel(const float* __restrict__ h, const int* __restrict__ batch) {
    int f = threadIdx.x;  // 0..127
    int n0 = blockIdx.x * 256;
    int n1 = n0 + 256; if (n1 > NNODES) n1 = NNODES;
    if (n0 >= NNODES) return;
    float acc = 0.f, c = 0.f;
    int curg = batch[n0];
    for (int n = n0; n < n1; n++) {
        int g = batch[n];
        if (g != curg) {
            atomicAdd(&g_pool[curg * HID + f], acc);
            if (f == 0) atomicAdd(&g_cnt[curg], c);
            acc = 0.f; c = 0.f; curg = g;
        }
        acc += h[(size_t)n * HID + f];
        c += 1.f;
    }
    atomicAdd(&g_pool[curg * HID + f], acc);
    if (f == 0) atomicAdd(&g_cnt[curg], c);
}

__global__ void final_kernel(const float* __restrict__ Wlin, const float* __restrict__ blin,
                             float* __restrict__ out) {
    int t = threadIdx.x;
    if (t >= NGRAPH * NCLASS) return;
    int g = t / NCLASS, c = t % NCLASS;
    float cnt = fmaxf(g_cnt[g], 1.f);
    float acc = blin[c];
#pragma unroll 8
    for (int f = 0; f < HID; f++)
        acc = fmaf(g_pool[g * HID + f] / cnt, Wlin[f * NCLASS + c], acc);
    out[t] = acc;
}

// ---------------------------------------------------------------------------
// Launch
// ---------------------------------------------------------------------------
extern "C" void kernel_launch(void* const* d_in, const int* in_sizes, int n_in,
                              void* d_out, int out_size) {
    const float* x     = (const float*)d_in[0];
    const int*   ei    = (const int*)d_in[1];
    const float* ea    = (const float*)d_in[2];
    const int*   batch = (const int*)d_in[3];
    const float* We1 = (const float*)d_in[4],  *be1 = (const float*)d_in[5];
    const float* W1  = (const float*)d_in[6],  *b1  = (const float*)d_in[7];
    const float* We2 = (const float*)d_in[8],  *be2 = (const float*)d_in[9];
    const float* W2  = (const float*)d_in[10], *b2  = (const float*)d_in[11];
    const float* We3 = (const float*)d_in[12], *be3 = (const float*)d_in[13];
    const float* W3  = (const float*)d_in[14], *b3  = (const float*)d_in[15];
    const float* Wlin = (const float*)d_in[16], *blin = (const float*)d_in[17];
    float* out = (float*)d_out;

    void *aggp, *hap, *hbp, *curp;
    cudaGetSymbolAddress(&aggp, g_agg);
    cudaGetSymbolAddress(&hap,  g_ha);
    cudaGetSymbolAddress(&hbp,  g_hb);
    cudaGetSymbolAddress(&curp, g_cur);
    float* agg = (float*)aggp;
    float* ha  = (float*)hap;
    float* hb  = (float*)hbp;

    cudaFuncSetAttribute(dense128, cudaFuncAttributeMaxDynamicSharedMemorySize, 98304);

    const int EBLK = (NEDGES + 255) / 256;
    const int G128_BLOCKS = (NNODES * 32 + 255) / 256;   // warp per node
    const int D128_BLOCKS = (NNODES + 63) / 64;

    // CSR build (reused by all 3 layers)
    cudaMemsetAsync(curp, 0, NNODES * sizeof(int), 0);
    hist_kernel<<<EBLK, 256>>>(ei);
    scan_kernel<<<1, 1024>>>();
    fill_kernel<<<EBLK, 256>>>(ei, ea);

    // Layer 1 (in = 7 feats)
    gather7<<<(NNODES + 255) / 256, 256>>>(x, We1, be1);
    dense7<<<(NNODES + 255) / 256, 128>>>(W1, b1);                    // -> g_ha

    // Layer 2
    gather128<<<G128_BLOCKS, 256>>>(ha, We2, be2, agg);
    dense128<<<D128_BLOCKS, 256, 98304>>>(agg, W2, b2, hb);           // -> g_hb

    // Layer 3
    gather128<<<G128_BLOCKS, 256>>>(hb, We3, be3, agg);
    dense128<<<D128_BLOCKS, 256, 98304>>>(agg, W3, b3, ha);           // -> g_ha

    // Mean pool + linear head
    pool_init<<<8, 128>>>();
    pool_kernel<<<(NNODES + 255) / 256, 128>>>(ha, batch);
    final_kernel<<<1, 64>>>(Wlin, blin, out);
}

// round 7
// speedup vs baseline: 1.4524x; 1.0148x over previous
#include <cuda_runtime.h>
#include <cuda_fp16.h>
#include <cstddef>

#define NNODES 100000
#define NEDGES 1600000
#define NFEAT  7
#define HID    128
#define NGRAPH 8
#define NCLASS 5

// ---------------------------------------------------------------------------
// Device-global scratch (allocation-free contract)
// ---------------------------------------------------------------------------
__device__ int    g_rowptr[NNODES + 1];
__device__ int    g_cur[NNODES];
__device__ int2   g_epack[NEDGES];        // CSR slot: {src, attr bits}
__device__ float  g_agg7[NNODES * NFEAT];
__device__ float  g_agg[NNODES * HID];
__device__ float  g_ha[NNODES * HID];
__device__ float  g_hb[NNODES * HID];
__device__ __half g_h16[NNODES * HID];    // fp16 copy of current h (neighbor reads)
__device__ float  g_pool[NGRAPH * HID];
__device__ float  g_cnt[NGRAPH];

// ---------------------------------------------------------------------------
// CSR build: histogram -> scan -> fill
// ---------------------------------------------------------------------------
__global__ void hist_kernel(const int* __restrict__ ei) {
    int e = blockIdx.x * blockDim.x + threadIdx.x;
    if (e < NEDGES) atomicAdd(&g_cur[ei[NEDGES + e]], 1);
}

__global__ void scan_kernel() {
    __shared__ int warp_sums[32];
    __shared__ int s_carry;
    int tid = threadIdx.x;
    int lane = tid & 31, wid = tid >> 5;
    if (tid == 0) s_carry = 0;
    __syncthreads();
    for (int base = 0; base < NNODES; base += 1024) {
        int i = base + tid;
        int v = (i < NNODES) ? g_cur[i] : 0;
        int incl = v;
#pragma unroll
        for (int o = 1; o < 32; o <<= 1) {
            int t = __shfl_up_sync(0xffffffffu, incl, o);
            if (lane >= o) incl += t;
        }
        if (lane == 31) warp_sums[wid] = incl;
        __syncthreads();
        if (wid == 0) {
            int ws = warp_sums[lane];
            int wincl = ws;
#pragma unroll
            for (int o = 1; o < 32; o <<= 1) {
                int t = __shfl_up_sync(0xffffffffu, wincl, o);
                if (lane >= o) wincl += t;
            }
            warp_sums[lane] = wincl - ws;
        }
        __syncthreads();
        int excl = incl - v + warp_sums[wid] + s_carry;
        if (i < NNODES) { g_rowptr[i] = excl; g_cur[i] = excl; }
        __syncthreads();
        if (tid == 1023) s_carry = excl + v;
        __syncthreads();
    }
    if (tid == 0) g_rowptr[NNODES] = NEDGES;
}

__global__ void fill_kernel(const int* __restrict__ ei, const float* __restrict__ ea) {
    int e = blockIdx.x * blockDim.x + threadIdx.x;
    if (e >= NEDGES) return;
    int d = ei[NEDGES + e];
    int pos = atomicAdd(&g_cur[d], 1);
    g_epack[pos] = make_int2(ei[e], __float_as_int(ea[e]));
}

// ---------------------------------------------------------------------------
// Layer 1 gather: thread per node, 7 features, 4-edge unroll
// ---------------------------------------------------------------------------
__global__ void gather7(const float* __restrict__ x, const float* __restrict__ We,
                        const float* __restrict__ be) {
    int n = blockIdx.x * blockDim.x + threadIdx.x;
    if (n >= NNODES) return;
    float w[NFEAT], bb[NFEAT], acc[NFEAT];
#pragma unroll
    for (int f = 0; f < NFEAT; f++) { w[f] = __ldg(&We[f]); bb[f] = __ldg(&be[f]); }
#pragma unroll
    for (int f = 0; f < NFEAT; f++) acc[f] = x[n * NFEAT + f];
    int beg = g_rowptr[n], end = g_rowptr[n + 1];
    int e = beg;
    for (; e + 3 < end; e += 4) {
        int2 p0 = __ldg(&g_epack[e]),     p1 = __ldg(&g_epack[e + 1]);
        int2 p2 = __ldg(&g_epack[e + 2]), p3 = __ldg(&g_epack[e + 3]);
        float a0 = __int_as_float(p0.y), a1 = __int_as_float(p1.y);
        float a2 = __int_as_float(p2.y), a3 = __int_as_float(p3.y);
        float v0[NFEAT], v1[NFEAT], v2[NFEAT], v3[NFEAT];
#pragma unroll
        for (int f = 0; f < NFEAT; f++) v0[f] = __ldg(&x[p0.x * NFEAT + f]);
#pragma unroll
        for (int f = 0; f < NFEAT; f++) v1[f] = __ldg(&x[p1.x * NFEAT + f]);
#pragma unroll
        for (int f = 0; f < NFEAT; f++) v2[f] = __ldg(&x[p2.x * NFEAT + f]);
#pragma unroll
        for (int f = 0; f < NFEAT; f++) v3[f] = __ldg(&x[p3.x * NFEAT + f]);
#pragma unroll
        for (int f = 0; f < NFEAT; f++) {
            acc[f] += fmaxf(v0[f] + fmaf(a0, w[f], bb[f]), 0.f)
                    + fmaxf(v1[f] + fmaf(a1, w[f], bb[f]), 0.f)
                    + fmaxf(v2[f] + fmaf(a2, w[f], bb[f]), 0.f)
                    + fmaxf(v3[f] + fmaf(a3, w[f], bb[f]), 0.f);
        }
    }
    for (; e < end; e++) {
        int2 p = __ldg(&g_epack[e]);
        float a = __int_as_float(p.y);
#pragma unroll
        for (int f = 0; f < NFEAT; f++)
            acc[f] += fmaxf(__ldg(&x[p.x * NFEAT + f]) + fmaf(a, w[f], bb[f]), 0.f);
    }
#pragma unroll
    for (int f = 0; f < NFEAT; f++) g_agg7[n * NFEAT + f] = acc[f];
}

// ---------------------------------------------------------------------------
// Layer 1 dense: writes fp32 h1 AND fp16 copy
// ---------------------------------------------------------------------------
__global__ void dense7(const float* __restrict__ W, const float* __restrict__ b) {
    __shared__ float sW[NFEAT * HID];
    __shared__ float sb[HID];
    __shared__ float sAgg[256 * NFEAT];
    int t = threadIdx.x;  // 0..127
    for (int i = t; i < NFEAT * HID; i += 128) sW[i] = W[i];
    sb[t] = b[t];

    int n0 = blockIdx.x * 256;
    int cnt = NNODES - n0; if (cnt > 256) cnt = 256;
    for (int i = t; i < cnt * NFEAT; i += 128) sAgg[i] = g_agg7[n0 * NFEAT + i];
    __syncthreads();

    for (int r = 0; r < cnt; r++) {
        float acc = sb[t];
#pragma unroll
        for (int k = 0; k < NFEAT; k++)
            acc = fmaf(sAgg[r * NFEAT + k], sW[k * HID + t], acc);
        float o = fmaxf(acc, 0.f);
        size_t idx = (size_t)(n0 + r) * HID + t;
        g_ha[idx]  = o;
        g_h16[idx] = __float2half_rn(o);
    }
}

// ---------------------------------------------------------------------------
// 128-feat gather: warp per node, fp16 neighbor rows, 8-edge unroll (MLP=8)
// self term from fp32 h; fp32 accumulators
// ---------------------------------------------------------------------------
__device__ __forceinline__ void acc_edge(float4& acc, uint2 v, float a,
                                         const float4& w, const float4& bb) {
    __half2 h0 = *reinterpret_cast<__half2*>(&v.x);
    __half2 h1 = *reinterpret_cast<__half2*>(&v.y);
    float2 f0 = __half22float2(h0);
    float2 f1 = __half22float2(h1);
    acc.x += fmaxf(f0.x + fmaf(a, w.x, bb.x), 0.f);
    acc.y += fmaxf(f0.y + fmaf(a, w.y, bb.y), 0.f);
    acc.z += fmaxf(f1.x + fmaf(a, w.z, bb.z), 0.f);
    acc.w += fmaxf(f1.y + fmaf(a, w.w, bb.w), 0.f);
}

__global__ void gather128(const float* __restrict__ h32, const float* __restrict__ We,
                          const float* __restrict__ be, float* __restrict__ aggout) {
    int warp = (blockIdx.x * blockDim.x + threadIdx.x) >> 5;
    int lane = threadIdx.x & 31;
    if (warp >= NNODES) return;
    float4 w  = __ldg(&((const float4*)We)[lane]);
    float4 bb = __ldg(&((const float4*)be)[lane]);
    int beg = __ldg(&g_rowptr[warp]);
    int end = __ldg(&g_rowptr[warp + 1]);
    const uint2* h16 = (const uint2*)g_h16;   // row = 32 * uint2 (4 halfs per lane)
    float4 acc = ((const float4*)h32)[(size_t)warp * 32 + lane];

    int e = beg;
    for (; e + 7 < end; e += 8) {
        int2 p[8];
#pragma unroll
        for (int i = 0; i < 8; i++) p[i] = __ldg(&g_epack[e + i]);
        uint2 v[8];
#pragma unroll
        for (int i = 0; i < 8; i++) v[i] = __ldg(&h16[(size_t)p[i].x * 32 + lane]);
#pragma unroll
        for (int i = 0; i < 8; i++)
            acc_edge(acc, v[i], __int_as_float(p[i].y), w, bb);
    }
    for (; e + 1 < end; e += 2) {
        int2 p0 = __ldg(&g_epack[e]), p1 = __ldg(&g_epack[e + 1]);
        uint2 v0 = __ldg(&h16[(size_t)p0.x * 32 + lane]);
        uint2 v1 = __ldg(&h16[(size_t)p1.x * 32 + lane]);
        acc_edge(acc, v0, __int_as_float(p0.y), w, bb);
        acc_edge(acc, v1, __int_as_float(p1.y), w, bb);
    }
    if (e < end) {
        int2 p0 = __ldg(&g_epack[e]);
        uint2 v0 = __ldg(&h16[(size_t)p0.x * 32 + lane]);
        acc_edge(acc, v0, __int_as_float(p0.y), w, bb);
    }
    ((float4*)aggout)[(size_t)warp * 32 + lane] = acc;
}

// ---------------------------------------------------------------------------
// Dense 128x128: out[n,:] = relu( A[n,:] @ W + b ); optional fp16 mirror
// ---------------------------------------------------------------------------
__global__ void dense128(const float* __restrict__ A, const float* __restrict__ W,
                         const float* __restrict__ b, float* __restrict__ out,
                         int write16) {
    extern __shared__ float sm[];
    float* sW = sm;              // 64KB
    float* sA = sm + HID * HID;  // 32KB
    int t = threadIdx.x;         // 0..255
    int m0 = blockIdx.x * 64;

    {
        float4* dW = (float4*)sW;
        const float4* gW = (const float4*)W;
        for (int i = t; i < HID * HID / 4; i += 256) dW[i] = gW[i];
    }
    {
        float4* dA = (float4*)sA;
        for (int i = t; i < 64 * 32; i += 256) {
            int r = i >> 5, c = i & 31;
            int n = m0 + r;
            float4 v = make_float4(0.f, 0.f, 0.f, 0.f);
            if (n < NNODES) v = ((const float4*)A)[(size_t)n * 32 + c];
            dA[i] = v;
        }
    }
    __syncthreads();

    int tn = t & 31;
    int tm = t >> 5;
    float acc[8][4];
#pragma unroll
    for (int i = 0; i < 8; i++)
#pragma unroll
        for (int j = 0; j < 4; j++) acc[i][j] = 0.f;

#pragma unroll 8
    for (int k4 = 0; k4 < 32; k4++) {
        float4 a4[8];
#pragma unroll
        for (int i = 0; i < 8; i++)
            a4[i] = ((float4*)(sA + (tm * 8 + i) * HID))[k4];
#pragma unroll
        for (int kk = 0; kk < 4; kk++) {
            float4 w4 = ((float4*)(sW + (k4 * 4 + kk) * HID))[tn];
#pragma unroll
            for (int i = 0; i < 8; i++) {
                float av = (kk == 0) ? a4[i].x : (kk == 1) ? a4[i].y
                         : (kk == 2) ? a4[i].z : a4[i].w;
                acc[i][0] = fmaf(av, w4.x, acc[i][0]);
                acc[i][1] = fmaf(av, w4.y, acc[i][1]);
                acc[i][2] = fmaf(av, w4.z, acc[i][2]);
                acc[i][3] = fmaf(av, w4.w, acc[i][3]);
            }
        }
    }

    float4 bb = __ldg(&((const float4*)b)[tn]);
#pragma unroll
    for (int i = 0; i < 8; i++) {
        int n = m0 + tm * 8 + i;
        if (n < NNODES) {
            float4 o;
            o.x = fmaxf(acc[i][0] + bb.x, 0.f);
            o.y = fmaxf(acc[i][1] + bb.y, 0.f);
            o.z = fmaxf(acc[i][2] + bb.z, 0.f);
            o.w = fmaxf(acc[i][3] + bb.w, 0.f);
            ((float4*)out)[(size_t)n * 32 + tn] = o;
            if (write16) {
                uint2 hv;
                __half2 p0 = __floats2half2_rn(o.x, o.y);
                __half2 p1 = __floats2half2_rn(o.z, o.w);
                hv.x = *reinterpret_cast<unsigned*>(&p0);
                hv.y = *reinterpret_cast<unsigned*>(&p1);
                ((uint2*)g_h16)[(size_t)n * 32 + tn] = hv;
            }
        }
    }
}

// ---------------------------------------------------------------------------
// Pooling + head
// ---------------------------------------------------------------------------
__global__ void pool_init() {
    int t = blockIdx.x * blockDim.x + threadIdx.x;
    if (t < NGRAPH * HID) g_pool[t] = 0.f;
    if (t < NGRAPH) g_cnt[t] = 0.f;
}

__global__ void pool_kernel(const float* __restrict__ h, const int* __restrict__ batch) {
    int f = threadIdx.x;  // 0..127
    int n0 = blockIdx.x * 256;
    int n1 = n0 + 256; if (n1 > NNODES) n1 = NNODES;
    if (n0 >= NNODES) return;
    float acc = 0.f, c = 0.f;
    int curg = batch[n0];
    for (int n = n0; n < n1; n++) {
        int g = batch[n];
        if (g != curg) {
            atomicAdd(&g_pool[curg * HID + f], acc);
            if (f == 0) atomicAdd(&g_cnt[curg], c);
            acc = 0.f; c = 0.f; curg = g;
        }
        acc += h[(size_t)n * HID + f];
        c += 1.f;
    }
    atomicAdd(&g_pool[curg * HID + f], acc);
    if (f == 0) atomicAdd(&g_cnt[curg], c);
}

__global__ void final_kernel(const float* __restrict__ Wlin, const float* __restrict__ blin,
                             float* __restrict__ out) {
    int t = threadIdx.x;
    if (t >= NGRAPH * NCLASS) return;
    int g = t / NCLASS, c = t % NCLASS;
    float cnt = fmaxf(g_cnt[g], 1.f);
    float acc = blin[c];
#pragma unroll 8
    for (int f = 0; f < HID; f++)
        acc = fmaf(g_pool[g * HID + f] / cnt, Wlin[f * NCLASS + c], acc);
    out[t] = acc;
}

// ---------------------------------------------------------------------------
// Launch
// ---------------------------------------------------------------------------
extern "C" void kernel_launch(void* const* d_in, const int* in_sizes, int n_in,
                              void* d_out, int out_size) {
    const float* x     = (const float*)d_in[0];
    const int*   ei    = (const int*)d_in[1];
    const float* ea    = (const float*)d_in[2];
    const int*   batch = (const int*)d_in[3];
    const float* We1 = (const float*)d_in[4],  *be1 = (const float*)d_in[5];
    const float* W1  = (const float*)d_in[6],  *b1  = (const float*)d_in[7];
    const float* We2 = (const float*)d_in[8],  *be2 = (const float*)d_in[9];
    const float* W2  = (const float*)d_in[10], *b2  = (const float*)d_in[11];
    const float* We3 = (const float*)d_in[12], *be3 = (const float*)d_in[13];
    const float* W3  = (const float*)d_in[14], *b3  = (const float*)d_in[15];
    const float* Wlin = (const float*)d_in[16], *blin = (const float*)d_in[17];
    float* out = (float*)d_out;

    void *aggp, *hap, *hbp, *curp;
    cudaGetSymbolAddress(&aggp, g_agg);
    cudaGetSymbolAddress(&hap,  g_ha);
    cudaGetSymbolAddress(&hbp,  g_hb);
    cudaGetSymbolAddress(&curp, g_cur);
    float* agg = (float*)aggp;
    float* ha  = (float*)hap;
    float* hb  = (float*)hbp;

    cudaFuncSetAttribute(dense128, cudaFuncAttributeMaxDynamicSharedMemorySize, 98304);

    const int EBLK = (NEDGES + 255) / 256;
    const int G128_BLOCKS = (NNODES * 32 + 255) / 256;   // warp per node
    const int D128_BLOCKS = (NNODES + 63) / 64;

    // CSR build (reused by all 3 layers)
    cudaMemsetAsync(curp, 0, NNODES * sizeof(int), 0);
    hist_kernel<<<EBLK, 256>>>(ei);
    scan_kernel<<<1, 1024>>>();
    fill_kernel<<<EBLK, 256>>>(ei, ea);

    // Layer 1 (in = 7 feats)
    gather7<<<(NNODES + 255) / 256, 256>>>(x, We1, be1);
    dense7<<<(NNODES + 255) / 256, 128>>>(W1, b1);            // -> g_ha + g_h16

    // Layer 2
    gather128<<<G128_BLOCKS, 256>>>(ha, We2, be2, agg);       // reads g_h16 (h1)
    dense128<<<D128_BLOCKS, 256, 98304>>>(agg, W2, b2, hb, 1);// -> g_hb + g_h16

    // Layer 3
    gather128<<<G128_BLOCKS, 256>>>(hb, We3, be3, agg);       // reads g_h16 (h2)
    dense128<<<D128_BLOCKS, 256, 98304>>>(agg, W3, b3, ha, 0);// -> g_ha

    // Mean pool + linear head
    pool_init<<<8, 128>>>();
    pool_kernel<<<(NNODES + 255) / 256, 128>>>(ha, batch);
    final_kernel<<<1, 64>>>(Wlin, blin, out);
}